// round 1
// baseline (speedup 1.0000x reference)
#include <cuda_runtime.h>

#define THRESH 0.85f
#define NB 4
#define ND 16
#define NN 4096
#define CHUNK 512
#define SSTR 20   // floats per n-row in smem (pad 16->20: 80B, 16B-aligned, bank-shift 16)

typedef unsigned long long u64;

// transposed seg: [b][n][d], d contiguous (1 MB scratch)
__device__ float g_segT[NB * NN * ND];

__device__ __forceinline__ void ffma2(u64& acc, u64 a, u64 b) {
    asm("fma.rn.f32x2 %0, %1, %2, %0;" : "+l"(acc) : "l"(a), "l"(b));
}
__device__ __forceinline__ u64 pack2(float lo, float hi) {
    u64 r; asm("mov.b64 %0, {%1, %2};" : "=l"(r) : "f"(lo), "f"(hi)); return r;
}
__device__ __forceinline__ float2 unpack2(u64 v) {
    float2 f; asm("mov.b64 {%0, %1}, %2;" : "=f"(f.x), "=f"(f.y) : "l"(v)); return f;
}
__device__ __forceinline__ u64 add2(u64 a, u64 b) {
    u64 r; asm("add.rn.f32x2 %0, %1, %2;" : "=l"(r) : "l"(a), "l"(b)); return r;
}

struct WBuf { float4 v[2][4]; };  // [row-in-pair][sub-step]

// ---------------- prologue: seg [b][d][n] -> segT [b][n][d] ----------------
__global__ void __launch_bounds__(256) seg_transpose_kernel(const float* __restrict__ seg) {
    int idx = blockIdx.x * blockDim.x + threadIdx.x;   // 0 .. NB*NN-1
    int b = idx >> 12;
    int n = idx & (NN - 1);
    float vals[ND];
#pragma unroll
    for (int d = 0; d < ND; ++d)
        vals[d] = seg[(((size_t)b * ND + d) << 12) + n];
    float4* dst = reinterpret_cast<float4*>(g_segT + (size_t)idx * ND);
#pragma unroll
    for (int q = 0; q < 4; ++q)
        dst[q] = make_float4(vals[4*q], vals[4*q+1], vals[4*q+2], vals[4*q+3]);
}

// ---------------- main kernel helpers ----------------
__device__ __forceinline__ void loadW(WBuf& wb, const float* p0, const float* p1, int n) {
#pragma unroll
    for (int sub = 0; sub < 4; ++sub) {
        wb.v[0][sub] = __ldg(reinterpret_cast<const float4*>(p0 + n + sub * 8));
        wb.v[1][sub] = __ldg(reinterpret_cast<const float4*>(p1 + n + sub * 8));
    }
}

__device__ __forceinline__ void computeSS(const WBuf& wb, u64* acc0, u64* acc1,
                                          const float* sseg, int nloc, int par, u64 ones) {
#pragma unroll
    for (int sub = 0; sub < 4; ++sub) {
#pragma unroll
        for (int k = 0; k < 4; ++k) {
            const int nidx = nloc + sub * 8 + par * 4 + k;
            const ulonglong2* sp = reinterpret_cast<const ulonglong2*>(sseg + nidx * SSTR);
            ulonglong2 sA = sp[0];
            ulonglong2 sB = sp[1];
            ulonglong2 sC = sp[2];
            ulonglong2 sD = sp[3];
            float w0 = reinterpret_cast<const float*>(&wb.v[0][sub])[k];
            float w1 = reinterpret_cast<const float*>(&wb.v[1][sub])[k];
            float wt0 = (w0 > THRESH) ? w0 : 0.0f;
            float wt1 = (w1 > THRESH) ? w1 : 0.0f;
            u64 a0 = pack2(wt0, wt0);
            u64 a1 = pack2(wt1, wt1);
            ffma2(acc0[0], a0, sA.x);  ffma2(acc1[0], a1, sA.x);
            ffma2(acc0[1], a0, sA.y);  ffma2(acc1[1], a1, sA.y);
            ffma2(acc0[2], a0, sB.x);  ffma2(acc1[2], a1, sB.x);
            ffma2(acc0[3], a0, sB.y);  ffma2(acc1[3], a1, sB.y);
            ffma2(acc0[4], a0, sC.x);  ffma2(acc1[4], a1, sC.x);
            ffma2(acc0[5], a0, sC.y);  ffma2(acc1[5], a1, sC.y);
            ffma2(acc0[6], a0, sD.x);  ffma2(acc1[6], a1, sD.x);
            ffma2(acc0[7], a0, sD.y);  ffma2(acc1[7], a1, sD.y);
            // fold row-sum into 9th accumulator: acc8.lo += wt
            ffma2(acc0[8], a0, ones);  ffma2(acc1[8], a1, ones);
        }
    }
}

// ---------------- main kernel ----------------
// grid = 128 blocks (4 b * 32 row-tiles), block = 128 threads.
// Warp covers 32 rows: 16 lane-pairs, each pair owns 2 rows; lane parity splits
// each 8-n group into two float4 halves (coalesced 32B per row per pair).
__global__ void __launch_bounds__(128, 1) regu_main_kernel(const float* __restrict__ W,
                                                           float* __restrict__ out) {
    __shared__ float sseg[CHUNK * SSTR];
    const int tid  = threadIdx.x;
    const int b    = blockIdx.x >> 5;
    const int m_base = (blockIdx.x & 31) << 7;
    const int warp = tid >> 5;
    const int lane = tid & 31;
    const int pair = lane >> 1;
    const int par  = lane & 1;
    const int row0 = m_base + warp * 32 + pair * 2;

    const float* p0 = W + ((size_t)b * NN + row0) * NN + par * 4;
    const float* p1 = p0 + NN;

    u64 acc0[9], acc1[9];
#pragma unroll
    for (int j = 0; j < 9; ++j) { acc0[j] = 0ull; acc1[j] = 0ull; }
    const u64 ones = pack2(1.0f, 0.0f);

    WBuf A, B;
    loadW(A, p0, p1, 0);   // prime the pipeline

    for (int ch = 0; ch < NN / CHUNK; ++ch) {
        __syncthreads();
        // stage seg chunk: segT is [n][16] contiguous -> smem [n][20]
        const float4* segTb =
            reinterpret_cast<const float4*>(g_segT + ((size_t)b * NN + ch * CHUNK) * ND);
#pragma unroll
        for (int i = 0; i < (CHUNK * 4) / 128; ++i) {
            int ii = i * 128 + tid;
            int nl = ii >> 2, q = ii & 3;
            *reinterpret_cast<float4*>(&sseg[nl * SSTR + q * 4]) = segTb[ii];
        }
        __syncthreads();

        const int base = ch * CHUNK;
#pragma unroll 1
        for (int s = 0; s < CHUNK / 32; s += 2) {
            int n1 = base + (s + 1) * 32;
            int n2 = base + (s + 2) * 32;
            if (n2 >= NN) n2 = 0;               // harmless clamp on final prefetch
            loadW(B, p0, p1, n1);
            computeSS(A, acc0, acc1, sseg, s * 32, par, ones);
            loadW(A, p0, p1, n2);               // crosses chunk boundary: W isn't smem-gated
            computeSS(B, acc0, acc1, sseg, (s + 1) * 32, par, ones);
        }
    }

    // combine n-halves across lane pairs (xor 1)
#pragma unroll
    for (int j = 0; j < 9; ++j) {
        acc0[j] = add2(acc0[j], __shfl_xor_sync(0xffffffffu, acc0[j], 1));
        acc1[j] = add2(acc1[j], __shfl_xor_sync(0xffffffffu, acc1[j], 1));
    }

    // even lane writes row0 (acc0), odd lane writes row0+1 (acc1)
    const int m = row0 + par;
    float res[ND];
    float s_sum;
#pragma unroll
    for (int j = 0; j < 8; ++j) {
        float2 f0 = unpack2(acc0[j]);
        float2 f1 = unpack2(acc1[j]);
        res[2 * j]     = par ? f1.x : f0.x;
        res[2 * j + 1] = par ? f1.y : f0.y;
    }
    {
        float2 f0 = unpack2(acc0[8]);
        float2 f1 = unpack2(acc1[8]);
        s_sum = par ? f1.x : f0.x;
    }
    const float inv = 1.0f / s_sum;
    float* ob = out + (size_t)b * ND * NN + m;
#pragma unroll
    for (int d = 0; d < ND; ++d)
        ob[(size_t)d * NN] = res[d] * inv;     // coalesced: m consecutive across lanes
}

extern "C" void kernel_launch(void* const* d_in, const int* in_sizes, int n_in,
                              void* d_out, int out_size) {
    const float* seg = (const float*)d_in[0];   // [4,16,64,64] fp32
    const float* W   = (const float*)d_in[1];   // [4,4096,4096] fp32
    float* out = (float*)d_out;                 // [4,16,64,64] fp32
    (void)in_sizes; (void)n_in; (void)out_size;

    seg_transpose_kernel<<<(NB * NN) / 256, 256>>>(seg);
    regu_main_kernel<<<128, 128>>>(W, out);
}

// round 2
// speedup vs baseline: 1.8988x; 1.8988x over previous
#include <cuda_runtime.h>

#define THRESH 0.85f
#define NB 4
#define ND 16
#define NN 4096
#define CHUNK 512
#define NSTEP 32
#define STEPS (CHUNK / NSTEP)   // 16

typedef unsigned long long u64;

// transposed seg: [b][n][d], d contiguous (1 MB scratch)
__device__ float g_segT[NB * NN * ND];

__device__ __forceinline__ void ffma2(u64& acc, u64 a, u64 b) {
    asm("fma.rn.f32x2 %0, %1, %2, %0;" : "+l"(acc) : "l"(a), "l"(b));
}
__device__ __forceinline__ u64 pack2(float lo, float hi) {
    u64 r; asm("mov.b64 %0, {%1, %2};" : "=l"(r) : "f"(lo), "f"(hi)); return r;
}
__device__ __forceinline__ float2 unpack2(u64 v) {
    float2 f; asm("mov.b64 {%0, %1}, %2;" : "=f"(f.x), "=f"(f.y) : "l"(v)); return f;
}
__device__ __forceinline__ u64 add2(u64 a, u64 b) {
    u64 r; asm("add.rn.f32x2 %0, %1, %2;" : "=l"(r) : "l"(a), "l"(b)); return r;
}

// ---------------- prologue: seg [b][d][n] -> segT [b][n][d] ----------------
__global__ void __launch_bounds__(256) seg_transpose_kernel(const float* __restrict__ seg) {
    int idx = blockIdx.x * blockDim.x + threadIdx.x;   // 0 .. NB*NN-1
    int b = idx >> 12;
    int n = idx & (NN - 1);
    float vals[ND];
#pragma unroll
    for (int d = 0; d < ND; ++d)
        vals[d] = seg[(((size_t)b * ND + d) << 12) + n];
    float4* dst = reinterpret_cast<float4*>(g_segT + (size_t)idx * ND);
#pragma unroll
    for (int q = 0; q < 4; ++q)
        dst[q] = make_float4(vals[4*q], vals[4*q+1], vals[4*q+2], vals[4*q+3]);
}

// ---------------- main kernel ----------------
struct WBuf { float4 w0, w1; };   // this lane's 4 n-values for its 2 rows

__device__ __forceinline__ void loadW(WBuf& wb, const float* p0, const float* p1, int n) {
    wb.w0 = __ldg(reinterpret_cast<const float4*>(p0 + n));
    wb.w1 = __ldg(reinterpret_cast<const float4*>(p1 + n));
}

// acc0/acc1: 9 f32x2 each = 16 d-values + (rowsum, 0) for rows r0 / r1.
__device__ __forceinline__ void computeSS(const WBuf& wb, u64* acc0, u64* acc1,
                                          const char* ssegB, int nloc, int j, u64 ones) {
    const float* w0f = reinterpret_cast<const float*>(&wb.w0);
    const float* w1f = reinterpret_cast<const float*>(&wb.w1);
#pragma unroll
    for (int k = 0; k < 4; ++k) {
        const int n = nloc + j * 4 + k;                 // local n within chunk
        const unsigned ofs = ((unsigned)n << 6) ^ ((unsigned)j << 4);  // swizzled byte offset
        float v0 = w0f[k], v1 = w1f[k];
        float wt0 = (v0 > THRESH) ? v0 : 0.0f;
        float wt1 = (v1 > THRESH) ? v1 : 0.0f;
        u64 a0 = pack2(wt0, wt0);
        u64 a1 = pack2(wt1, wt1);
#pragma unroll
        for (int q = 0; q < 4; ++q) {
            ulonglong2 sv = *reinterpret_cast<const ulonglong2*>(ssegB + (ofs ^ (q << 4)));
            ffma2(acc0[2*q],     a0, sv.x);
            ffma2(acc0[2*q + 1], a0, sv.y);
            ffma2(acc1[2*q],     a1, sv.x);
            ffma2(acc1[2*q + 1], a1, sv.y);
        }
        ffma2(acc0[8], a0, ones);
        ffma2(acc1[8], a1, ones);
    }
}

__device__ __forceinline__ void storeRow(const u64* acc, float* out, int b, int m) {
    float2 s8 = unpack2(acc[8]);
    const float inv = 1.0f / s8.x;
    float* ob = out + (size_t)b * ND * NN + m;
#pragma unroll
    for (int i = 0; i < 8; ++i) {
        float2 f = unpack2(acc[i]);
        ob[(size_t)(2*i)     * NN] = f.x * inv;
        ob[(size_t)(2*i + 1) * NN] = f.y * inv;
    }
}

// grid = 512 blocks (4 b * 128 row-tiles of 32 rows), block = 128 threads.
// Warp = 4 groups of 8 lanes; group g owns rows {base+2g, base+2g+1};
// lane j owns n-offsets 4j..4j+3 of each 32-n superstep (coalesced LDG.128,
// 4 lines per instruction = 128B/wavefront floor).
__global__ void __launch_bounds__(128, 4) regu_main_kernel(const float* __restrict__ W,
                                                           float* __restrict__ out) {
    __shared__ __align__(1024) float sseg[CHUNK * ND];   // 32KB, XOR-swizzled 16B slots
    const int tid  = threadIdx.x;
    const int warp = tid >> 5;
    const int lane = tid & 31;
    const int g    = lane >> 3;
    const int j    = lane & 7;
    const int b    = blockIdx.x >> 7;
    const int r0   = ((blockIdx.x & 127) << 5) + warp * 8 + g * 2;

    const float* p0 = W + ((size_t)b * NN + r0) * NN + j * 4;
    const float* p1 = p0 + NN;

    u64 acc0[9], acc1[9];
#pragma unroll
    for (int i = 0; i < 9; ++i) { acc0[i] = 0ull; acc1[i] = 0ull; }
    const u64 ones = pack2(1.0f, 0.0f);

    const char* ssegB = reinterpret_cast<const char*>(sseg);

    WBuf b0, b1, b2, b3;
    loadW(b0, p0, p1, 0);        // prefetch depth 2 (supersteps 0 and 1)
    loadW(b1, p0, p1, NSTEP);

    for (int ch = 0; ch < NN / CHUNK; ++ch) {
        __syncthreads();
        // stage seg chunk with XOR swizzle: slot s = n*4+q -> phys = s ^ ((s>>4)&7)
        const float4* segTb =
            reinterpret_cast<const float4*>(g_segT + ((size_t)b * NN + ch * CHUNK) * ND);
#pragma unroll
        for (int i = 0; i < (CHUNK * 4) / 128; ++i) {
            int s = i * 128 + tid;
            float4 v = segTb[s];
            int phys = s ^ ((s >> 4) & 7);
            *reinterpret_cast<float4*>(const_cast<char*>(ssegB) + ((size_t)phys << 4)) = v;
        }
        __syncthreads();

        const int base = ch * CHUNK;
#pragma unroll 1
        for (int s = 0; s < STEPS; s += 4) {
            int n2 = base + (s + 2) * NSTEP; if (n2 >= NN) n2 -= NN;
            loadW(b2, p0, p1, n2);
            computeSS(b0, acc0, acc1, ssegB, (s + 0) * NSTEP, j, ones);
            int n3 = base + (s + 3) * NSTEP; if (n3 >= NN) n3 -= NN;
            loadW(b3, p0, p1, n3);
            computeSS(b1, acc0, acc1, ssegB, (s + 1) * NSTEP, j, ones);
            int n4 = base + (s + 4) * NSTEP; if (n4 >= NN) n4 -= NN;
            loadW(b0, p0, p1, n4);
            computeSS(b2, acc0, acc1, ssegB, (s + 2) * NSTEP, j, ones);
            int n5 = base + (s + 5) * NSTEP; if (n5 >= NN) n5 -= NN;
            loadW(b1, p0, p1, n5);
            computeSS(b3, acc0, acc1, ssegB, (s + 3) * NSTEP, j, ones);
        }
    }

    // reduce over the 8 lanes of each group (xor 1,2,4 stays within the group)
#pragma unroll
    for (int m = 1; m <= 4; m <<= 1) {
#pragma unroll
        for (int i = 0; i < 9; ++i) {
            acc0[i] = add2(acc0[i], __shfl_xor_sync(0xffffffffu, acc0[i], m));
            acc1[i] = add2(acc1[i], __shfl_xor_sync(0xffffffffu, acc1[i], m));
        }
    }

    if (j == 0) {
        storeRow(acc0, out, b, r0);
    } else if (j == 1) {
        storeRow(acc1, out, b, r0 + 1);
    }
}

extern "C" void kernel_launch(void* const* d_in, const int* in_sizes, int n_in,
                              void* d_out, int out_size) {
    const float* seg = (const float*)d_in[0];   // [4,16,64,64] fp32
    const float* W   = (const float*)d_in[1];   // [4,4096,4096] fp32
    float* out = (float*)d_out;                 // [4,16,64,64] fp32
    (void)in_sizes; (void)n_in; (void)out_size;

    seg_transpose_kernel<<<(NB * NN) / 256, 256>>>(seg);
    regu_main_kernel<<<512, 128>>>(W, out);
}